// round 1
// baseline (speedup 1.0000x reference)
#include <cuda_runtime.h>
#include <math.h>

#define EPS 1e-9f

// ---- problem dims ----
#define BATCH   64
#define HW1     64      // conv1 spatial (64x64), 64 channels
#define HW2     28      // conv2 spatial
#define NROUTES 6272    // 8*28*28
#define NCAPS   10
#define ODIM    16
#define JDIM    8

// ---- device scratch (allocation-free rule: static globals) ----
__device__ float g_h[(size_t)BATCH*64*HW1*HW1];     // conv1 out, 64 MB
__device__ float g_u[(size_t)BATCH*NROUTES*JDIM];   // squashed primary caps, 12.8 MB
__device__ float g_bij[(size_t)BATCH*NROUTES*NCAPS];// routing logits, 16 MB
__device__ float g_s[BATCH*NCAPS*ODIM];             // 10240 floats
__device__ float g_v[BATCH*NCAPS*ODIM];             // 10240 floats

// ============================================================
// zero s accumulator
// ============================================================
__global__ void zero_s_kernel() {
    int i = blockIdx.x * 256 + threadIdx.x;
    if (i < BATCH*NCAPS*ODIM) g_s[i] = 0.f;
}

// ============================================================
// conv1: (64,1,64,64) -> (64,64,64,64), k5 pad2 + bias + relu
// block: one batch, 16x16 spatial tile; thread computes all 64 oc
// ============================================================
__global__ __launch_bounds__(256) void conv1_kernel(
    const float* __restrict__ x, const float* __restrict__ w,
    const float* __restrict__ bias)
{
    __shared__ float xs[20][20];
    __shared__ float ws[64*25];
    __shared__ float bs[64];
    int b   = blockIdx.z;
    int ty0 = blockIdx.y * 16, tx0 = blockIdx.x * 16;
    int tid = threadIdx.y * 16 + threadIdx.x;

    for (int i = tid; i < 64*25; i += 256) ws[i] = w[i];
    if (tid < 64) bs[tid] = bias[tid];

    const float* xb = x + (size_t)b * HW1 * HW1;
    for (int i = tid; i < 400; i += 256) {
        int r = i / 20, c = i % 20;
        int gy = ty0 + r - 2, gx = tx0 + c - 2;
        float v = 0.f;
        if (gy >= 0 && gy < HW1 && gx >= 0 && gx < HW1) v = xb[gy*HW1 + gx];
        xs[r][c] = v;
    }
    __syncthreads();

    int ty = threadIdx.y, tx = threadIdx.x;
    float in[25];
#pragma unroll
    for (int kh = 0; kh < 5; kh++)
#pragma unroll
        for (int kw = 0; kw < 5; kw++)
            in[kh*5+kw] = xs[ty+kh][tx+kw];

    int y = ty0 + ty, xc = tx0 + tx;
    float* hout = g_h + ((size_t)b*64)*HW1*HW1 + y*HW1 + xc;
#pragma unroll 4
    for (int oc = 0; oc < 64; oc++) {
        float acc = bs[oc];
        const float* wo = &ws[oc*25];
#pragma unroll
        for (int k = 0; k < 25; k++) acc = fmaf(in[k], wo[k], acc);
        hout[(size_t)oc*HW1*HW1] = fmaxf(acc, 0.f);
    }
}

// ============================================================
// conv2: (64,64,64,64) -> u (64,6272,8)
// k9 s2 VALID + bias, then capsule squash fused in epilogue.
// block: (batch b, two output rows 2t,2t+1) x 28 ow x 64 oc
// threads 224 = 28 ow-groups x 8 oc-groups; micro-tile 8oc x 2oh
// ============================================================
#define WPAD 68
__global__ __launch_bounds__(224) void conv2_kernel(
    const float* __restrict__ w, const float* __restrict__ bias)
{
    __shared__ float ws[81*WPAD];   // [q][oc], padded
    __shared__ float ins[11*64];    // input rows 4t..4t+10

    int b   = blockIdx.y;
    int t   = blockIdx.x;           // 0..13
    int tid = threadIdx.x;          // 0..223
    int ocg = tid & 7;              // capsule group 0..7
    int ow  = tid >> 3;             // 0..27
    int ow2 = ow * 2;

    float acc0[8], acc1[8];
#pragma unroll
    for (int c = 0; c < 8; c++) { acc0[c] = 0.f; acc1[c] = 0.f; }

    const float* hb = g_h + (size_t)b*64*HW1*HW1;

    for (int ic = 0; ic < 64; ic++) {
        __syncthreads();
        // stage weights transposed: ws[q*WPAD + oc] = w[oc][ic][q]
        for (int i = tid; i < 64*81; i += 224) {
            int oc = i / 81, q = i % 81;
            ws[q*WPAD + oc] = w[(size_t)(oc*64 + ic)*81 + q];
        }
        // stage input rows 4t..4t+10 (11 x 64)
        const float* hrow = hb + (size_t)ic*HW1*HW1 + (4*t)*HW1;
        for (int i = tid; i < 11*64; i += 224) ins[i] = hrow[i];
        __syncthreads();

#pragma unroll
        for (int kh = 0; kh < 9; kh++) {
#pragma unroll
            for (int kw = 0; kw < 9; kw++) {
                int q = kh*9 + kw;
                float4 wa = *(const float4*)&ws[q*WPAD + ocg*8];
                float4 wb = *(const float4*)&ws[q*WPAD + ocg*8 + 4];
                float in0 = ins[kh*64 + ow2 + kw];
                float in1 = ins[(kh+2)*64 + ow2 + kw];
                acc0[0] = fmaf(in0, wa.x, acc0[0]); acc1[0] = fmaf(in1, wa.x, acc1[0]);
                acc0[1] = fmaf(in0, wa.y, acc0[1]); acc1[1] = fmaf(in1, wa.y, acc1[1]);
                acc0[2] = fmaf(in0, wa.z, acc0[2]); acc1[2] = fmaf(in1, wa.z, acc1[2]);
                acc0[3] = fmaf(in0, wa.w, acc0[3]); acc1[3] = fmaf(in1, wa.w, acc1[3]);
                acc0[4] = fmaf(in0, wb.x, acc0[4]); acc1[4] = fmaf(in1, wb.x, acc1[4]);
                acc0[5] = fmaf(in0, wb.y, acc0[5]); acc1[5] = fmaf(in1, wb.y, acc1[5]);
                acc0[6] = fmaf(in0, wb.z, acc0[6]); acc1[6] = fmaf(in1, wb.z, acc1[6]);
                acc0[7] = fmaf(in0, wb.w, acc0[7]); acc1[7] = fmaf(in1, wb.w, acc1[7]);
            }
        }
    }

    // epilogue: bias + squash over the 8-dim capsule, write u
    float bvals[8];
#pragma unroll
    for (int c = 0; c < 8; c++) bvals[c] = bias[ocg*8 + c];

    int oh0 = 2*t;
#pragma unroll
    for (int r = 0; r < 2; r++) {
        float* a = (r == 0) ? acc0 : acc1;
        float msq = 0.f;
#pragma unroll
        for (int c = 0; c < 8; c++) { a[c] += bvals[c]; msq = fmaf(a[c], a[c], msq); }
        float mag   = sqrtf(msq + EPS);
        float scale = msq / (1.f + msq) / (mag + EPS);
        int n = ocg*(HW2*HW2) + (oh0+r)*HW2 + ow;
        float* up = g_u + ((size_t)b*NROUTES + n)*JDIM;
#pragma unroll
        for (int c = 0; c < 8; c++) up[c] = a[c] * scale;
    }
}

// ============================================================
// routing sweep: recompute u_hat, update b_ij, softmax(o),
// accumulate s partials in smem, one atomicAdd flush per block.
// block: 32 n's x all 64 b; threads 640 = 64 b x 10 o
// iter 0: c = 0.1 (softmax of zeros)
// iter 1: bnew = uh.v0 (old b=0), store b_ij
// iter 2: bnew = b_ij + uh.v1
// ============================================================
__global__ __launch_bounds__(640) void route_kernel(
    const float* __restrict__ W, int iter)
{
    __shared__ float Ws[NCAPS*ODIM*JDIM];   // 1280
    __shared__ float spart[BATCH*NCAPS*ODIM]; // 10240
    __shared__ float bex[BATCH][NCAPS];     // 640

    int tid = threadIdx.x;
    int bb  = tid / 10;
    int o   = tid % 10;

    for (int i = tid; i < BATCH*NCAPS*ODIM; i += 640) spart[i] = 0.f;

    int n0 = blockIdx.x * 32;
    for (int nn = 0; nn < 32; nn++) {
        int n = n0 + nn;
        __syncthreads();
        const float* Wn = W + (size_t)n * (NCAPS*ODIM*JDIM);
        for (int i = tid; i < NCAPS*ODIM*JDIM; i += 640) Ws[i] = Wn[i];
        __syncthreads();

        const float4* up = (const float4*)(g_u + ((size_t)bb*NROUTES + n)*JDIM);
        float4 u0 = up[0], u1 = up[1];

        float uh[16];
#pragma unroll
        for (int i = 0; i < 16; i++) {
            const float* wr = &Ws[(o*16 + i)*8];
            float4 wa = *(const float4*)wr;
            float4 wb = *(const float4*)(wr + 4);
            float t0 = fmaf(wa.x, u0.x, wa.y * u0.y);
            float t1 = fmaf(wa.z, u0.z, wa.w * u0.w);
            float t2 = fmaf(wb.x, u1.x, wb.y * u1.y);
            float t3 = fmaf(wb.z, u1.z, wb.w * u1.w);
            uh[i] = (t0 + t1) + (t2 + t3);
        }

        float c;
        if (iter == 0) {
            c = 0.1f;
        } else {
            const float* vp = g_v + (bb*NCAPS + o)*ODIM;
            float bnew = 0.f;
#pragma unroll
            for (int i = 0; i < 16; i++) bnew = fmaf(uh[i], vp[i], bnew);
            size_t bidx = ((size_t)bb*NROUTES + n)*NCAPS + o;
            if (iter == 2) bnew += g_bij[bidx];
            else           g_bij[bidx] = bnew;
            bex[bb][o] = bnew;
            __syncthreads();
            float m = -1e30f;
#pragma unroll
            for (int k = 0; k < 10; k++) m = fmaxf(m, bex[bb][k]);
            float denom = 0.f;
#pragma unroll
            for (int k = 0; k < 10; k++) denom += expf(bex[bb][k] - m);
            c = expf(bnew - m) / denom;
        }

        float* sp = &spart[(bb*NCAPS + o)*ODIM];
#pragma unroll
        for (int i = 0; i < 16; i++) sp[i] = fmaf(c, uh[i], sp[i]);
    }
    __syncthreads();
    for (int i = tid; i < BATCH*NCAPS*ODIM; i += 640) atomicAdd(&g_s[i], spart[i]);
}

// ============================================================
// squash s -> v (or final output); re-zeros g_s for next sweep
// 640 threads, one per (b,o)
// ============================================================
__global__ __launch_bounds__(640) void squash_v_kernel(float* __restrict__ out, int final_iter)
{
    int tid = threadIdx.x;  // 0..639 = b*10+o
    float s[16]; float msq = 0.f;
    const float* sp = g_s + tid*16;
#pragma unroll
    for (int i = 0; i < 16; i++) { s[i] = sp[i]; msq = fmaf(s[i], s[i], msq); }
    float mag   = sqrtf(msq + EPS);
    float scale = msq / (1.f + msq) / (mag + EPS);
    float* vp = final_iter ? (out + tid*16) : (g_v + tid*16);
#pragma unroll
    for (int i = 0; i < 16; i++) vp[i] = s[i] * scale;
#pragma unroll
    for (int i = 0; i < 16; i++) g_s[tid*16 + i] = 0.f;
}

// ============================================================
extern "C" void kernel_launch(void* const* d_in, const int* in_sizes, int n_in,
                              void* d_out, int out_size)
{
    const float* x   = (const float*)d_in[0];
    const float* c1w = (const float*)d_in[1];
    const float* c1b = (const float*)d_in[2];
    const float* pw  = (const float*)d_in[3];
    const float* pb  = (const float*)d_in[4];
    const float* W   = (const float*)d_in[5];
    float* out = (float*)d_out;

    zero_s_kernel<<<40, 256>>>();
    conv1_kernel<<<dim3(4,4,64), dim3(16,16)>>>(x, c1w, c1b);
    conv2_kernel<<<dim3(14,64), 224>>>(pw, pb);

    route_kernel<<<196, 640>>>(W, 0);
    squash_v_kernel<<<1, 640>>>(out, 0);
    route_kernel<<<196, 640>>>(W, 1);
    squash_v_kernel<<<1, 640>>>(out, 0);
    route_kernel<<<196, 640>>>(W, 2);
    squash_v_kernel<<<1, 640>>>(out, 1);
}

// round 2
// speedup vs baseline: 2.2173x; 2.2173x over previous
#include <cuda_runtime.h>
#include <math.h>

#define EPS 1e-9f

#define BATCH   64
#define HW1     64
#define HW2     28
#define NROUTES 6272
#define NCAPS   10
#define ODIM    16
#define JDIM    8

#define RBLOCKS 392      // route blocks
#define NPER    16       // n's per route block  (392*16 = 6272)
#define WROW    132      // padded W row (16*8 floats -> 132)

typedef unsigned long long u64;

__device__ float g_h[(size_t)BATCH*64*HW1*HW1];                 // conv1 out
__device__ float g_u[(size_t)BATCH*NROUTES*JDIM];               // primary caps
__device__ float g_v[BATCH*NCAPS*ODIM];                         // v (v0, then v0+v1)
__device__ float g_spart[(size_t)RBLOCKS*BATCH*NCAPS*ODIM];     // per-block s partials

// ---------- packed fp32x2 helpers ----------
__device__ __forceinline__ u64 pack2(float x) {
    u64 r; asm("mov.b64 %0, {%1, %1};" : "=l"(r) : "f"(x)); return r;
}
__device__ __forceinline__ void ffma2(u64& d, u64 a, u64 b) {
    asm("fma.rn.f32x2 %0, %1, %2, %0;" : "+l"(d) : "l"(a), "l"(b));
}
__device__ __forceinline__ float2 unpack2(u64 a) {
    float2 f; asm("mov.b64 {%0, %1}, %2;" : "=f"(f.x), "=f"(f.y) : "l"(a)); return f;
}

// ============================================================
// conv1: (64,1,64,64) -> (64,64,64,64), k5 pad2 + bias + relu
// ============================================================
__global__ __launch_bounds__(256) void conv1_kernel(
    const float* __restrict__ x, const float* __restrict__ w,
    const float* __restrict__ bias)
{
    __shared__ float xs[20][20];
    __shared__ float ws[64*25];
    __shared__ float bs[64];
    int b   = blockIdx.z;
    int ty0 = blockIdx.y * 16, tx0 = blockIdx.x * 16;
    int tid = threadIdx.y * 16 + threadIdx.x;

    for (int i = tid; i < 64*25; i += 256) ws[i] = w[i];
    if (tid < 64) bs[tid] = bias[tid];

    const float* xb = x + (size_t)b * HW1 * HW1;
    for (int i = tid; i < 400; i += 256) {
        int r = i / 20, c = i % 20;
        int gy = ty0 + r - 2, gx = tx0 + c - 2;
        float v = 0.f;
        if (gy >= 0 && gy < HW1 && gx >= 0 && gx < HW1) v = xb[gy*HW1 + gx];
        xs[r][c] = v;
    }
    __syncthreads();

    int ty = threadIdx.y, tx = threadIdx.x;
    float in[25];
#pragma unroll
    for (int kh = 0; kh < 5; kh++)
#pragma unroll
        for (int kw = 0; kw < 5; kw++)
            in[kh*5+kw] = xs[ty+kh][tx+kw];

    int y = ty0 + ty, xc = tx0 + tx;
    float* hout = g_h + ((size_t)b*64)*HW1*HW1 + y*HW1 + xc;
#pragma unroll 4
    for (int oc = 0; oc < 64; oc++) {
        float acc = bs[oc];
        const float* wo = &ws[oc*25];
#pragma unroll
        for (int k = 0; k < 25; k++) acc = fmaf(in[k], wo[k], acc);
        hout[(size_t)oc*HW1*HW1] = fmaxf(acc, 0.f);
    }
}

// ============================================================
// conv2: k9 s2 + bias + capsule squash -> g_u
// packed f32x2 FFMA; weights staged bank-perfect (1 wf / LDS.128)
// block: (b, row-pair t) x 224 threads = 28 ow x 8 ocg
// ============================================================
__global__ __launch_bounds__(224) void conv2_kernel(
    const float* __restrict__ w, const float* __restrict__ bias)
{
    __shared__ float wsA[81*32];   // [q][ocg*4 + c], c=0..3  (oc = ocg*8+c)
    __shared__ float wsB[81*32];   // c=4..7
    __shared__ float ins[11*64];

    int b   = blockIdx.y;
    int t   = blockIdx.x;
    int tid = threadIdx.x;
    int ocg = tid & 7;
    int ow  = tid >> 3;
    int ow2 = ow * 2;

    u64 a0[4], a1[4];
#pragma unroll
    for (int k = 0; k < 4; k++) { a0[k] = 0ull; a1[k] = 0ull; }

    const float* hb = g_h + (size_t)b*64*HW1*HW1;

    for (int ic = 0; ic < 64; ic++) {
        __syncthreads();
        for (int i = tid; i < 64*81; i += 224) {
            int oc = i / 81, q = i - oc*81;
            float val = w[(size_t)(oc*64 + ic)*81 + q];
            int c7 = oc & 7, grp = oc >> 3;
            if (c7 < 4) wsA[q*32 + grp*4 + c7]       = val;
            else        wsB[q*32 + grp*4 + (c7 - 4)] = val;
        }
        const float* hrow = hb + (size_t)ic*HW1*HW1 + (4*t)*HW1;
        for (int i = tid; i < 11*64; i += 224) ins[i] = hrow[i];
        __syncthreads();

#pragma unroll
        for (int kh = 0; kh < 9; kh++) {
#pragma unroll
            for (int kw = 0; kw < 9; kw++) {
                int q = kh*9 + kw;
                const u64* WA = (const u64*)&wsA[q*32 + ocg*4];
                const u64* WB = (const u64*)&wsB[q*32 + ocg*4];
                u64 wa0 = WA[0], wa1 = WA[1];
                u64 wb0 = WB[0], wb1 = WB[1];
                u64 i0 = pack2(ins[kh*64 + ow2 + kw]);
                u64 i1 = pack2(ins[(kh+2)*64 + ow2 + kw]);
                ffma2(a0[0], i0, wa0); ffma2(a0[1], i0, wa1);
                ffma2(a0[2], i0, wb0); ffma2(a0[3], i0, wb1);
                ffma2(a1[0], i1, wa0); ffma2(a1[1], i1, wa1);
                ffma2(a1[2], i1, wb0); ffma2(a1[3], i1, wb1);
            }
        }
    }

    float bvals[8];
#pragma unroll
    for (int c = 0; c < 8; c++) bvals[c] = bias[ocg*8 + c];

    int oh0 = 2*t;
#pragma unroll
    for (int r = 0; r < 2; r++) {
        u64* ap = r ? a1 : a0;
        float a[8];
#pragma unroll
        for (int k = 0; k < 4; k++) {
            float2 f = unpack2(ap[k]);
            a[2*k] = f.x + bvals[2*k];
            a[2*k+1] = f.y + bvals[2*k+1];
        }
        float msq = 0.f;
#pragma unroll
        for (int c = 0; c < 8; c++) msq = fmaf(a[c], a[c], msq);
        float mag   = sqrtf(msq + EPS);
        float scale = msq / (1.f + msq) / (mag + EPS);
        int n = ocg*(HW2*HW2) + (oh0+r)*HW2 + ow;
        float* up = g_u + ((size_t)b*NROUTES + n)*JDIM;
        float4 o0 = make_float4(a[0]*scale, a[1]*scale, a[2]*scale, a[3]*scale);
        float4 o1 = make_float4(a[4]*scale, a[5]*scale, a[6]*scale, a[7]*scale);
        *(float4*)up       = o0;
        *(float4*)(up + 4) = o1;
    }
}

// ============================================================
// routing sweep. thread = (bb, o); 640 threads; 16 n per block.
// u_hat recomputed from W (double-buffered smem, padded rows).
// s accumulated in REGISTERS across n; per-block partials out.
// iter0: c = 0.1 exactly. iter>0: logits = uh . g_v (g_v holds
// v0 for iter1, v0+v1 for iter2 -> no b_ij storage needed).
// ============================================================
__global__ __launch_bounds__(640) void route_kernel(
    const float* __restrict__ W, int iter)
{
    __shared__ float Ws[2][NCAPS*WROW];
    __shared__ float ex[BATCH][NCAPS];

    int tid = threadIdx.x;
    int bb  = tid / 10;
    int o   = tid - bb*10;
    int n0  = blockIdx.x * NPER;

    float v[16];
    if (iter > 0) {
        const float4* vp = (const float4*)(g_v + (bb*NCAPS + o)*ODIM);
#pragma unroll
        for (int k = 0; k < 4; k++) {
            float4 f = vp[k];
            v[4*k] = f.x; v[4*k+1] = f.y; v[4*k+2] = f.z; v[4*k+3] = f.w;
        }
    }

    float acc[16];
#pragma unroll
    for (int i = 0; i < 16; i++) acc[i] = 0.f;

    // prefetch n0
    float2 wpre = *(const float2*)(W + (size_t)n0*(NCAPS*ODIM*JDIM) + 2*tid);
    const float4* up0 = (const float4*)(g_u + ((size_t)bb*NROUTES + n0)*JDIM);
    float4 upa = up0[0], upb = up0[1];

    int buf = 0;
    for (int nn = 0; nn < NPER; nn++) {
        // store prefetched W chunk into padded smem
        {
            int f  = 2*tid;
            int os = f >> 7;        // /128
            int r  = f & 127;
            *(float2*)&Ws[buf][os*WROW + r] = wpre;
        }
        __syncthreads();   // Ws ready; also orders ex reuse across n

        float4 ua = upa, ub = upb;
        if (nn < NPER-1) {
            const float* Wn = W + (size_t)(n0+nn+1)*(NCAPS*ODIM*JDIM);
            wpre = *(const float2*)(Wn + 2*tid);
            const float4* up = (const float4*)(g_u + ((size_t)bb*NROUTES + n0+nn+1)*JDIM);
            upa = up[0]; upb = up[1];
        }

        float uh[16];
        const float* wrow = &Ws[buf][o*WROW];
#pragma unroll
        for (int i = 0; i < 16; i++) {
            float4 wa = *(const float4*)(wrow + i*8);
            float4 wb = *(const float4*)(wrow + i*8 + 4);
            float s = wa.x * ua.x;
            s = fmaf(wa.y, ua.y, s); s = fmaf(wa.z, ua.z, s); s = fmaf(wa.w, ua.w, s);
            s = fmaf(wb.x, ub.x, s); s = fmaf(wb.y, ub.y, s);
            s = fmaf(wb.z, ub.z, s); s = fmaf(wb.w, ub.w, s);
            uh[i] = s;
        }

        float c;
        if (iter == 0) {
            c = 0.1f;
        } else {
            float bnew = 0.f;
#pragma unroll
            for (int i = 0; i < 16; i++) bnew = fmaf(uh[i], v[i], bnew);
            float e = __expf(bnew);   // |bnew| <= ~8, no max-sub needed
            ex[bb][o] = e;
            __syncthreads();
            float denom = 0.f;
#pragma unroll
            for (int k = 0; k < 10; k++) denom += ex[bb][k];
            c = __fdividef(e, denom);
        }
#pragma unroll
        for (int i = 0; i < 16; i++) acc[i] = fmaf(c, uh[i], acc[i]);

        buf ^= 1;
    }

    float* sp = g_spart + ((size_t)blockIdx.x*(BATCH*NCAPS) + bb*NCAPS + o)*ODIM;
#pragma unroll
    for (int i = 0; i < 16; i += 4)
        *(float4*)(sp + i) = make_float4(acc[i], acc[i+1], acc[i+2], acc[i+3]);
}

// ============================================================
// reduce per-block partials -> s; squash -> v / out.
// 2560 threads: (b,o) x 4 quads; shfl over the 4 quads for ||s||^2
// mode 0: g_v = v0 ; mode 1: g_v += v1 (forms v0+v1) ; mode 2: out
// ============================================================
__global__ __launch_bounds__(256) void squash_v_kernel(float* __restrict__ out, int mode)
{
    int tid  = blockIdx.x*256 + threadIdx.x;   // 0..2559
    int boq  = tid >> 2;
    int quad = tid & 3;

    float4 s = make_float4(0.f, 0.f, 0.f, 0.f);
    const float* base = g_spart + boq*ODIM + quad*4;
#pragma unroll 4
    for (int p = 0; p < RBLOCKS; p++) {
        float4 t = *(const float4*)(base + (size_t)p*(BATCH*NCAPS*ODIM));
        s.x += t.x; s.y += t.y; s.z += t.z; s.w += t.w;
    }

    float part = s.x*s.x + s.y*s.y + s.z*s.z + s.w*s.w;
    part += __shfl_xor_sync(0xffffffff, part, 1);
    part += __shfl_xor_sync(0xffffffff, part, 2);
    float msq   = part;
    float mag   = sqrtf(msq + EPS);
    float scale = msq / (1.f + msq) / (mag + EPS);
    float4 vv = make_float4(s.x*scale, s.y*scale, s.z*scale, s.w*scale);

    if (mode == 0) {
        *(float4*)(g_v + boq*ODIM + quad*4) = vv;
    } else if (mode == 1) {
        float4 old = *(const float4*)(g_v + boq*ODIM + quad*4);
        old.x += vv.x; old.y += vv.y; old.z += vv.z; old.w += vv.w;
        *(float4*)(g_v + boq*ODIM + quad*4) = old;
    } else {
        *(float4*)(out + boq*ODIM + quad*4) = vv;
    }
}

// ============================================================
extern "C" void kernel_launch(void* const* d_in, const int* in_sizes, int n_in,
                              void* d_out, int out_size)
{
    const float* x   = (const float*)d_in[0];
    const float* c1w = (const float*)d_in[1];
    const float* c1b = (const float*)d_in[2];
    const float* pw  = (const float*)d_in[3];
    const float* pb  = (const float*)d_in[4];
    const float* W   = (const float*)d_in[5];
    float* out = (float*)d_out;

    conv1_kernel<<<dim3(4,4,64), dim3(16,16)>>>(x, c1w, c1b);
    conv2_kernel<<<dim3(14,64), 224>>>(pw, pb);

    route_kernel<<<RBLOCKS, 640>>>(W, 0);
    squash_v_kernel<<<10, 256>>>(out, 0);
    route_kernel<<<RBLOCKS, 640>>>(W, 1);
    squash_v_kernel<<<10, 256>>>(out, 1);
    route_kernel<<<RBLOCKS, 640>>>(W, 2);
    squash_v_kernel<<<10, 256>>>(out, 2);
}

// round 3
// speedup vs baseline: 3.0592x; 1.3797x over previous
#include <cuda_runtime.h>
#include <math.h>

#define EPS 1e-9f

#define BATCH   64
#define HW1     64
#define HW2     28
#define NROUTES 6272
#define NCAPS   10
#define ODIM    16
#define JDIM    8

#define RBLOCKS 392
#define NPER    16
#define WROW    132

typedef unsigned long long u64;

__device__ float g_h[(size_t)BATCH*64*HW1*HW1];    // conv1 out
__device__ float g_u[(size_t)BATCH*NROUTES*JDIM];  // primary caps
__device__ float g_v[BATCH*NCAPS*ODIM];            // v0, then v0+v1
__device__ float g_s[BATCH*NCAPS*ODIM];            // routing accumulator

// ---------- packed fp32x2 helpers ----------
__device__ __forceinline__ u64 pack2(float x) {
    u64 r; asm("mov.b64 %0, {%1, %1};" : "=l"(r) : "f"(x)); return r;
}
__device__ __forceinline__ void ffma2(u64& d, u64 a, u64 b) {
    asm("fma.rn.f32x2 %0, %1, %2, %0;" : "+l"(d) : "l"(a), "l"(b));
}
__device__ __forceinline__ float2 unpack2(u64 a) {
    float2 f; asm("mov.b64 {%0, %1}, %2;" : "=f"(f.x), "=f"(f.y) : "l"(a)); return f;
}

// ============================================================
__global__ void zero_s_kernel() {
    int i = blockIdx.x * 256 + threadIdx.x;
    if (i < BATCH*NCAPS*ODIM) g_s[i] = 0.f;
}

// ============================================================
// conv1: (64,1,64,64) -> (64,64,64,64), k5 pad2 + bias + relu
// ============================================================
__global__ __launch_bounds__(256) void conv1_kernel(
    const float* __restrict__ x, const float* __restrict__ w,
    const float* __restrict__ bias)
{
    __shared__ float xs[20][20];
    __shared__ float ws[64*25];
    __shared__ float bs[64];
    int b   = blockIdx.z;
    int ty0 = blockIdx.y * 16, tx0 = blockIdx.x * 16;
    int tid = threadIdx.y * 16 + threadIdx.x;

    for (int i = tid; i < 64*25; i += 256) ws[i] = w[i];
    if (tid < 64) bs[tid] = bias[tid];

    const float* xb = x + (size_t)b * HW1 * HW1;
    for (int i = tid; i < 400; i += 256) {
        int r = i / 20, c = i % 20;
        int gy = ty0 + r - 2, gx = tx0 + c - 2;
        float v = 0.f;
        if (gy >= 0 && gy < HW1 && gx >= 0 && gx < HW1) v = xb[gy*HW1 + gx];
        xs[r][c] = v;
    }
    __syncthreads();

    int ty = threadIdx.y, tx = threadIdx.x;
    float in[25];
#pragma unroll
    for (int kh = 0; kh < 5; kh++)
#pragma unroll
        for (int kw = 0; kw < 5; kw++)
            in[kh*5+kw] = xs[ty+kh][tx+kw];

    int y = ty0 + ty, xc = tx0 + tx;
    float* hout = g_h + ((size_t)b*64)*HW1*HW1 + y*HW1 + xc;
#pragma unroll 4
    for (int oc = 0; oc < 64; oc++) {
        float acc = bs[oc];
        const float* wo = &ws[oc*25];
#pragma unroll
        for (int k = 0; k < 25; k++) acc = fmaf(in[k], wo[k], acc);
        hout[(size_t)oc*HW1*HW1] = fmaxf(acc, 0.f);
    }
}

// ============================================================
// conv2: k9 s2 + bias + capsule squash -> g_u, packed f32x2.
// block: (b, 4 output rows) x 224 threads = 28 ow x 8 ocg.
// grid (7, 64) — weight staging amortized over 4 rows.
// ============================================================
__global__ __launch_bounds__(224) void conv2_kernel(
    const float* __restrict__ w, const float* __restrict__ bias)
{
    __shared__ float wsA[81*32];   // [q][ocg*4 + c], c=0..3
    __shared__ float wsB[81*32];   // c=4..7
    __shared__ float ins[15*64];   // input rows 8t..8t+14

    int b   = blockIdx.y;
    int t   = blockIdx.x;          // 0..6 -> output rows 4t..4t+3
    int tid = threadIdx.x;
    int ocg = tid & 7;
    int ow  = tid >> 3;
    int ow2 = ow * 2;

    u64 acc[4][4];
#pragma unroll
    for (int r = 0; r < 4; r++)
#pragma unroll
        for (int k = 0; k < 4; k++) acc[r][k] = 0ull;

    const float* hb = g_h + (size_t)b*64*HW1*HW1;

    for (int ic = 0; ic < 64; ic++) {
        __syncthreads();
        for (int i = tid; i < 64*81; i += 224) {
            int oc = i / 81, q = i - oc*81;
            float val = w[(size_t)(oc*64 + ic)*81 + q];
            int c7 = oc & 7, grp = oc >> 3;
            if (c7 < 4) wsA[q*32 + grp*4 + c7]       = val;
            else        wsB[q*32 + grp*4 + (c7 - 4)] = val;
        }
        const float* hrow = hb + (size_t)ic*HW1*HW1 + (8*t)*HW1;
        for (int i = tid; i < 15*64; i += 224) ins[i] = hrow[i];
        __syncthreads();

#pragma unroll
        for (int kh = 0; kh < 9; kh++) {
#pragma unroll
            for (int kw = 0; kw < 9; kw++) {
                int q = kh*9 + kw;
                const u64* WA = (const u64*)&wsA[q*32 + ocg*4];
                const u64* WB = (const u64*)&wsB[q*32 + ocg*4];
                u64 wa0 = WA[0], wa1 = WA[1];
                u64 wb0 = WB[0], wb1 = WB[1];
#pragma unroll
                for (int r = 0; r < 4; r++) {
                    u64 iv = pack2(ins[(kh + 2*r)*64 + ow2 + kw]);
                    ffma2(acc[r][0], iv, wa0); ffma2(acc[r][1], iv, wa1);
                    ffma2(acc[r][2], iv, wb0); ffma2(acc[r][3], iv, wb1);
                }
            }
        }
    }

    float bvals[8];
#pragma unroll
    for (int c = 0; c < 8; c++) bvals[c] = bias[ocg*8 + c];

#pragma unroll
    for (int r = 0; r < 4; r++) {
        float a[8];
#pragma unroll
        for (int k = 0; k < 4; k++) {
            float2 f = unpack2(acc[r][k]);
            a[2*k]   = f.x + bvals[2*k];
            a[2*k+1] = f.y + bvals[2*k+1];
        }
        float msq = 0.f;
#pragma unroll
        for (int c = 0; c < 8; c++) msq = fmaf(a[c], a[c], msq);
        float mag   = sqrtf(msq + EPS);
        float scale = msq / (1.f + msq) / (mag + EPS);
        int n = ocg*(HW2*HW2) + (4*t + r)*HW2 + ow;
        float* up = g_u + ((size_t)b*NROUTES + n)*JDIM;
        *(float4*)up       = make_float4(a[0]*scale, a[1]*scale, a[2]*scale, a[3]*scale);
        *(float4*)(up + 4) = make_float4(a[4]*scale, a[5]*scale, a[6]*scale, a[7]*scale);
    }
}

// ============================================================
// routing sweep. thread = (bb, o); 640 threads; 16 n per block.
// s accumulated in registers, flushed once via atomicAdd.
// iter0: c = 0.1. iter>0: logits = uh . g_v  (g_v = v0 or v0+v1)
// ============================================================
__global__ __launch_bounds__(640) void route_kernel(
    const float* __restrict__ W, int iter)
{
    __shared__ float Ws[2][NCAPS*WROW];
    __shared__ float ex[BATCH][NCAPS];

    int tid = threadIdx.x;
    int bb  = tid / 10;
    int o   = tid - bb*10;
    int n0  = blockIdx.x * NPER;

    float v[16];
    if (iter > 0) {
        const float4* vp = (const float4*)(g_v + (bb*NCAPS + o)*ODIM);
#pragma unroll
        for (int k = 0; k < 4; k++) {
            float4 f = vp[k];
            v[4*k] = f.x; v[4*k+1] = f.y; v[4*k+2] = f.z; v[4*k+3] = f.w;
        }
    }

    float acc[16];
#pragma unroll
    for (int i = 0; i < 16; i++) acc[i] = 0.f;

    float2 wpre = *(const float2*)(W + (size_t)n0*(NCAPS*ODIM*JDIM) + 2*tid);
    const float4* up0 = (const float4*)(g_u + ((size_t)bb*NROUTES + n0)*JDIM);
    float4 upa = up0[0], upb = up0[1];

    int buf = 0;
    for (int nn = 0; nn < NPER; nn++) {
        {
            int f  = 2*tid;
            int os = f >> 7;
            int r  = f & 127;
            *(float2*)&Ws[buf][os*WROW + r] = wpre;
        }
        __syncthreads();

        float4 ua = upa, ub = upb;
        if (nn < NPER-1) {
            const float* Wn = W + (size_t)(n0+nn+1)*(NCAPS*ODIM*JDIM);
            wpre = *(const float2*)(Wn + 2*tid);
            const float4* up = (const float4*)(g_u + ((size_t)bb*NROUTES + n0+nn+1)*JDIM);
            upa = up[0]; upb = up[1];
        }

        float uh[16];
        const float* wrow = &Ws[buf][o*WROW];
#pragma unroll
        for (int i = 0; i < 16; i++) {
            float4 wa = *(const float4*)(wrow + i*8);
            float4 wb = *(const float4*)(wrow + i*8 + 4);
            float s = wa.x * ua.x;
            s = fmaf(wa.y, ua.y, s); s = fmaf(wa.z, ua.z, s); s = fmaf(wa.w, ua.w, s);
            s = fmaf(wb.x, ub.x, s); s = fmaf(wb.y, ub.y, s);
            s = fmaf(wb.z, ub.z, s); s = fmaf(wb.w, ub.w, s);
            uh[i] = s;
        }

        float c;
        if (iter == 0) {
            c = 0.1f;
        } else {
            float bnew = 0.f;
#pragma unroll
            for (int i = 0; i < 16; i++) bnew = fmaf(uh[i], v[i], bnew);
            float e = __expf(bnew);
            ex[bb][o] = e;
            __syncthreads();
            float denom = 0.f;
#pragma unroll
            for (int k = 0; k < 10; k++) denom += ex[bb][k];
            c = __fdividef(e, denom);
        }
#pragma unroll
        for (int i = 0; i < 16; i++) acc[i] = fmaf(c, uh[i], acc[i]);

        buf ^= 1;
    }

    float* sp = g_s + (bb*NCAPS + o)*ODIM;
#pragma unroll
    for (int i = 0; i < 16; i++) atomicAdd(&sp[i], acc[i]);
}

// ============================================================
// squash s -> v / out; zero s for the next sweep.
// 2560 threads = (b,o) x 4 quads
// mode 0: g_v = v0 ; mode 1: g_v += v1 ; mode 2: write out
// ============================================================
__global__ __launch_bounds__(256) void squash_v_kernel(float* __restrict__ out, int mode)
{
    int tid  = blockIdx.x*256 + threadIdx.x;
    int boq  = tid >> 2;
    int quad = tid & 3;

    float4 s = *(const float4*)(g_s + boq*ODIM + quad*4);
    *(float4*)(g_s + boq*ODIM + quad*4) = make_float4(0.f,0.f,0.f,0.f);

    float part = s.x*s.x + s.y*s.y + s.z*s.z + s.w*s.w;
    part += __shfl_xor_sync(0xffffffff, part, 1);
    part += __shfl_xor_sync(0xffffffff, part, 2);
    float msq   = part;
    float mag   = sqrtf(msq + EPS);
    float scale = msq / (1.f + msq) / (mag + EPS);
    float4 vv = make_float4(s.x*scale, s.y*scale, s.z*scale, s.w*scale);

    if (mode == 0) {
        *(float4*)(g_v + boq*ODIM + quad*4) = vv;
    } else if (mode == 1) {
        float4 old = *(const float4*)(g_v + boq*ODIM + quad*4);
        old.x += vv.x; old.y += vv.y; old.z += vv.z; old.w += vv.w;
        *(float4*)(g_v + boq*ODIM + quad*4) = old;
    } else {
        *(float4*)(out + boq*ODIM + quad*4) = vv;
    }
}

// ============================================================
extern "C" void kernel_launch(void* const* d_in, const int* in_sizes, int n_in,
                              void* d_out, int out_size)
{
    const float* x   = (const float*)d_in[0];
    const float* c1w = (const float*)d_in[1];
    const float* c1b = (const float*)d_in[2];
    const float* pw  = (const float*)d_in[3];
    const float* pb  = (const float*)d_in[4];
    const float* W   = (const float*)d_in[5];
    float* out = (float*)d_out;

    zero_s_kernel<<<40, 256>>>();
    conv1_kernel<<<dim3(4,4,64), dim3(16,16)>>>(x, c1w, c1b);
    conv2_kernel<<<dim3(7,64), 224>>>(pw, pb);

    route_kernel<<<RBLOCKS, 640>>>(W, 0);
    squash_v_kernel<<<10, 256>>>(out, 0);
    route_kernel<<<RBLOCKS, 640>>>(W, 1);
    squash_v_kernel<<<10, 256>>>(out, 1);
    route_kernel<<<RBLOCKS, 640>>>(W, 2);
    squash_v_kernel<<<10, 256>>>(out, 2);
}